// round 15
// baseline (speedup 1.0000x reference)
#include <cuda_runtime.h>
#include <cuda_fp16.h>
#include <cstdint>

// ---------------------------------------------------------------------------
// Problem constants
// ---------------------------------------------------------------------------
constexpr int B_ = 8;
constexpr int C_ = 1024;     // M and K of both GEMMs
constexpr int T_ = 2048;     // N of both GEMMs
constexpr long NELEM = (long)B_ * C_ * T_;   // 16,777,216
constexpr long CT   = (long)C_ * T_;         // per-batch elements
constexpr int HB   = B_ / 2;                 // batches per half

// d_out layout: [ret | tap | ff1 | ff2], each NELEM floats.

// ---------------------------------------------------------------------------
// Scratch (device globals)
// ---------------------------------------------------------------------------
__device__ __half g_xa[(size_t)B_ * C_ * T_];   // fp16(tap) : shared B operand
__device__ __half g_w1[(size_t)C_ * C_];
__device__ __half g_w2[(size_t)C_ * C_];
__device__ __half g_w12[(size_t)C_ * C_];       // fp16(W2 @ W1)
__device__ float  g_b12[C_];                    // W2 @ b1 + b2

// ---------------------------------------------------------------------------
// helpers
// ---------------------------------------------------------------------------
__device__ __forceinline__ uint32_t smem_u32(const void* p) {
    uint32_t a;
    asm("{ .reg .u64 t; cvta.to.shared.u64 t, %1; cvt.u32.u64 %0, t; }"
        : "=r"(a) : "l"(p));
    return a;
}
__device__ __forceinline__ void cp_async16(uint32_t sdst, const void* gsrc) {
    asm volatile("cp.async.cg.shared.global [%0], [%1], 16;" :: "r"(sdst), "l"(gsrc));
}
__device__ __forceinline__ void cp_commit() {
    asm volatile("cp.async.commit_group;" ::: "memory");
}
template <int N>
__device__ __forceinline__ void cp_wait() {
    asm volatile("cp.async.wait_group %0;" :: "n"(N) : "memory");
}
__device__ __forceinline__ void ldsm_x4(uint32_t (&r)[4], uint32_t addr) {
    asm volatile("ldmatrix.sync.aligned.m8n8.x4.shared.b16 {%0,%1,%2,%3}, [%4];"
        : "=r"(r[0]), "=r"(r[1]), "=r"(r[2]), "=r"(r[3]) : "r"(addr));
}
__device__ __forceinline__ void ldsm_x4t(uint32_t (&r)[4], uint32_t addr) {
    asm volatile("ldmatrix.sync.aligned.m8n8.x4.trans.shared.b16 {%0,%1,%2,%3}, [%4];"
        : "=r"(r[0]), "=r"(r[1]), "=r"(r[2]), "=r"(r[3]) : "r"(addr));
}
__device__ __forceinline__ void mma_f16(float (&d)[4],
                                        const uint32_t (&a)[4],
                                        const uint32_t* b) {
    asm volatile(
        "mma.sync.aligned.m16n8k16.row.col.f32.f16.f16.f32 "
        "{%0,%1,%2,%3}, {%4,%5,%6,%7}, {%8,%9}, {%0,%1,%2,%3};"
        : "+f"(d[0]), "+f"(d[1]), "+f"(d[2]), "+f"(d[3])
        : "r"(a[0]), "r"(a[1]), "r"(a[2]), "r"(a[3]), "r"(b[0]), "r"(b[1]));
}

// ---------------------------------------------------------------------------
// Kernel: W1, W2 -> fp16 (vectorized)
// ---------------------------------------------------------------------------
__global__ void wconv_kernel(const float* __restrict__ W1,
                             const float* __restrict__ W2)
{
    int i = blockIdx.x * 256 + threadIdx.x;     // float4 index
    float4 v1 = reinterpret_cast<const float4*>(W1)[i];
    float4 v2 = reinterpret_cast<const float4*>(W2)[i];
    __half2 a, b;
    a.x = __float2half(v1.x); a.y = __float2half(v1.y);
    b.x = __float2half(v1.z); b.y = __float2half(v1.w);
    reinterpret_cast<__half2*>(g_w1)[i * 2]     = a;
    reinterpret_cast<__half2*>(g_w1)[i * 2 + 1] = b;
    a.x = __float2half(v2.x); a.y = __float2half(v2.y);
    b.x = __float2half(v2.z); b.y = __float2half(v2.w);
    reinterpret_cast<__half2*>(g_w2)[i * 2]     = a;
    reinterpret_cast<__half2*>(g_w2)[i * 2 + 1] = b;
}

// ---------------------------------------------------------------------------
// Kernel: b12 = W2 @ b1 + b2
// ---------------------------------------------------------------------------
__global__ void bias12_kernel(const float* __restrict__ W2,
                              const float* __restrict__ b1,
                              const float* __restrict__ b2)
{
    int row = blockIdx.x * 8 + (threadIdx.x >> 5);
    int lane = threadIdx.x & 31;
    const float* wr = W2 + (size_t)row * C_;
    float s = 0.0f;
    #pragma unroll 8
    for (int j = lane; j < C_; j += 32) s += wr[j] * b1[j];
    #pragma unroll
    for (int o = 16; o; o >>= 1) s += __shfl_xor_sync(0xFFFFFFFFu, s, o);
    if (lane == 0) g_b12[row] = s + b2[row];
}

// ---------------------------------------------------------------------------
// Kernel: half-batch 4:1 mean pool -> fp16 xa ONLY (critical path)
// ---------------------------------------------------------------------------
__global__ void poolxa_kernel(const float4* __restrict__ x4,
                              __half* __restrict__ xa)
{
    long i0 = ((long)blockIdx.x * 256 + threadIdx.x) * 2;
    float4 v0 = x4[i0];
    float4 v1 = x4[i0 + 1];
    float m0 = 0.25f * (v0.x + v0.y + v0.z + v0.w);
    float m1 = 0.25f * (v1.x + v1.y + v1.z + v1.w);
    __half2 h; h.x = __float2half(m0); h.y = __float2half(m1);
    *reinterpret_cast<__half2*>(xa + i0) = h;
}

// ---------------------------------------------------------------------------
// Kernel: tap = fp32(xa)  (off critical path; overlaps GEMM)
// ---------------------------------------------------------------------------
__global__ void tap_kernel(float* __restrict__ tap)
{
    long i = (long)blockIdx.x * 256 + threadIdx.x;   // 4 elems per thread
    uint2 raw = reinterpret_cast<const uint2*>(g_xa)[i];
    __half2 h0 = *reinterpret_cast<__half2*>(&raw.x);
    __half2 h1 = *reinterpret_cast<__half2*>(&raw.y);
    float4 o;
    o.x = __half2float(h0.x); o.y = __half2float(h0.y);
    o.z = __half2float(h1.x); o.w = __half2float(h1.y);
    reinterpret_cast<float4*>(tap)[i] = o;
}

// ---------------------------------------------------------------------------
// W12 GEMM: W12 = fp16(W2 @ W1)
// ---------------------------------------------------------------------------
constexpr int W_KC   = 64;
constexpr int W_ASTR = 144;
constexpr int W_BSTR = 272;
constexpr int W_OFB  = 64 * W_ASTR;               // 9216
constexpr int W_STAGE = W_OFB + W_KC * W_BSTR;    // 26624
constexpr int W_STAGES = 3;
constexpr int W_SMEM = W_STAGES * W_STAGE;        // 79872

__global__ __launch_bounds__(256, 1)
void w12_kernel()
{
    extern __shared__ __align__(128) char smem[];
    const uint32_t sb = smem_u32(smem);
    const int tid  = threadIdx.x;
    const int wid  = tid >> 5;
    const int lane = tid & 31;
    const int bn = blockIdx.x * 128;
    const int bm = blockIdx.y * 64;

    const int wm = (wid & 1) * 32;
    const int wn = (wid >> 1) * 32;

    auto load_stage = [&](int ch, int stg) {
        const int k0 = ch * W_KC;
        const uint32_t st = sb + stg * W_STAGE;
        #pragma unroll
        for (int i = 0; i < 2; i++) {
            int idx = tid + i * 256;
            int r = idx >> 3, c = idx & 7;
            cp_async16(st + r * W_ASTR + c * 16,
                       g_w2 + (size_t)(bm + r) * C_ + k0 + c * 8);
        }
        #pragma unroll
        for (int i = 0; i < 4; i++) {
            int idx = tid + i * 256;
            int r = idx >> 4, c = idx & 15;
            cp_async16(st + W_OFB + r * W_BSTR + c * 16,
                       g_w1 + (size_t)(k0 + r) * C_ + bn + c * 8);
        }
        cp_commit();
    };

    float acc[2][4][4];
    #pragma unroll
    for (int i = 0; i < 2; i++)
        #pragma unroll
        for (int j = 0; j < 4; j++)
            #pragma unroll
            for (int k = 0; k < 4; k++)
                acc[i][j][k] = 0.0f;

    load_stage(0, 0);
    load_stage(1, 1);

    const int lA_row = lane & 15;
    const int lA_kb  = (lane >> 4) * 16;
    const int lB_row = lane & 15;
    const int lB_nc  = (lane >> 4) * 8;

    for (int ch = 0; ch < C_ / W_KC; ch++) {
        cp_wait<W_STAGES - 2>();
        __syncthreads();
        if (ch + W_STAGES - 1 < C_ / W_KC)
            load_stage(ch + W_STAGES - 1, (ch + W_STAGES - 1) % W_STAGES);
        else
            cp_commit();
        const uint32_t st = sb + (ch % W_STAGES) * W_STAGE;

        #pragma unroll
        for (int ks = 0; ks < 4; ks++) {
            uint32_t b[4][2];
            #pragma unroll
            for (int nq = 0; nq < 2; nq++) {
                uint32_t r[4];
                uint32_t off = (uint32_t)((ks * 16 + lB_row) * W_BSTR
                                          + (wn + nq * 16 + lB_nc) * 2);
                ldsm_x4t(r, st + W_OFB + off);
                b[nq * 2 + 0][0] = r[0]; b[nq * 2 + 0][1] = r[1];
                b[nq * 2 + 1][0] = r[2]; b[nq * 2 + 1][1] = r[3];
            }
            #pragma unroll
            for (int mb = 0; mb < 2; mb++) {
                uint32_t a4[4];
                uint32_t off = (uint32_t)((wm + mb * 16 + lA_row) * W_ASTR
                                          + ks * 32 + lA_kb);
                ldsm_x4(a4, st + off);
                #pragma unroll
                for (int nb = 0; nb < 4; nb++)
                    mma_f16(acc[mb][nb], a4, b[nb]);
            }
        }
    }

    const int r_lo = lane >> 2;
    const int c_lo = (lane & 3) * 2;
    #pragma unroll
    for (int mb = 0; mb < 2; mb++) {
        int gr0 = bm + wm + mb * 16 + r_lo;
        int gr1 = gr0 + 8;
        #pragma unroll
        for (int nb = 0; nb < 4; nb++) {
            int col = bn + wn + nb * 8 + c_lo;
            __half2 h0; h0.x = __float2half(acc[mb][nb][0]);
                        h0.y = __float2half(acc[mb][nb][1]);
            __half2 h1; h1.x = __float2half(acc[mb][nb][2]);
                        h1.y = __float2half(acc[mb][nb][3]);
            *reinterpret_cast<__half2*>(g_w12 + (size_t)gr0 * C_ + col) = h0;
            *reinterpret_cast<__half2*>(g_w12 + (size_t)gr1 * C_ + col) = h1;
        }
    }
}

// ---------------------------------------------------------------------------
// GEMM (512-thr floor config; W/bias/out passed per launch; grid z = batch):
//   out[z] = W @ xa[z] + bias
// CTA tile 128x256, KC=32, 4-stage cp.async, 16 warps 4(M)x4(N), tile 32x64.
// ---------------------------------------------------------------------------
constexpr int KC = 32;
constexpr int A_STR = 80;
constexpr int B_STR = 528;
constexpr int OF_A = 0;
constexpr int OF_B = 128 * A_STR;                 // 10240
constexpr int STAGE_BYTES = OF_B + KC * B_STR;    // 27136
constexpr int STAGES = 4;
constexpr int GEMM_SMEM = STAGES * STAGE_BYTES;   // 108544
constexpr int NCHUNK = C_ / KC;                   // 32

__global__ __launch_bounds__(512, 1)
void gemm_kernel(const __half* __restrict__ W,
                 const float*  __restrict__ bias,
                 const __half* __restrict__ xa_base,
                 float* __restrict__ out_base)
{
    extern __shared__ __align__(128) char smem[];
    const uint32_t sb = smem_u32(smem);

    const int tid  = threadIdx.x;
    const int wid  = tid >> 5;
    const int lane = tid & 31;
    const int bn = blockIdx.x * 256;
    const int bm = blockIdx.y * 128;
    const int batch = blockIdx.z;

    const __half* Xb = xa_base + (size_t)batch * CT;
    float* out = out_base + (size_t)batch * CT;

    const int wm = (wid & 3) * 32;
    const int wn = (wid >> 2) * 64;

    const int a_r = tid >> 2;
    const int a_c = tid & 3;
    const int b_k = tid >> 5;
    const int b_c = tid & 31;

    auto load_stage = [&](int ch, int stg) {
        const int k0 = ch * KC;
        const uint32_t st = sb + stg * STAGE_BYTES;
        cp_async16(st + OF_A + a_r * A_STR + a_c * 16,
                   W + (size_t)(bm + a_r) * C_ + k0 + a_c * 8);
        #pragma unroll
        for (int i = 0; i < 2; i++) {
            int kr = b_k + i * 16;
            cp_async16(st + OF_B + kr * B_STR + b_c * 16,
                       Xb + (size_t)(k0 + kr) * T_ + bn + b_c * 8);
        }
        cp_commit();
    };

    float acc[2][8][4];
    #pragma unroll
    for (int i = 0; i < 2; i++)
        #pragma unroll
        for (int j = 0; j < 8; j++)
            #pragma unroll
            for (int k = 0; k < 4; k++)
                acc[i][j][k] = 0.0f;

    load_stage(0, 0);
    load_stage(1, 1);
    load_stage(2, 2);

    const int lA_row = lane & 15;
    const int lA_kb  = (lane >> 4) * 16;
    const int lB_row = lane & 15;
    const int lB_nc  = (lane >> 4) * 8;

    for (int ch = 0; ch < NCHUNK; ch++) {
        cp_wait<STAGES - 2>();
        __syncthreads();

        if (ch + STAGES - 1 < NCHUNK)
            load_stage(ch + STAGES - 1, (ch + STAGES - 1) % STAGES);
        else
            cp_commit();

        const uint32_t st = sb + (ch % STAGES) * STAGE_BYTES;

        #pragma unroll
        for (int ks = 0; ks < 2; ks++) {
            uint32_t b[8][2];
            #pragma unroll
            for (int nq = 0; nq < 4; nq++) {
                uint32_t r[4];
                uint32_t off = (uint32_t)((ks * 16 + lB_row) * B_STR
                                          + (wn + nq * 16 + lB_nc) * 2);
                ldsm_x4t(r, st + OF_B + off);
                b[nq * 2 + 0][0] = r[0]; b[nq * 2 + 0][1] = r[1];
                b[nq * 2 + 1][0] = r[2]; b[nq * 2 + 1][1] = r[3];
            }
            #pragma unroll
            for (int mb = 0; mb < 2; mb++) {
                uint32_t a4[4];
                uint32_t offA = (uint32_t)((wm + mb * 16 + lA_row) * A_STR
                                           + ks * 32 + lA_kb);
                ldsm_x4(a4, st + OF_A + offA);
                #pragma unroll
                for (int nb = 0; nb < 8; nb++)
                    mma_f16(acc[mb][nb], a4, b[nb]);
            }
        }
    }

    const int r_lo = lane >> 2;
    const int c_lo = (lane & 3) * 2;
    #pragma unroll
    for (int mb = 0; mb < 2; mb++) {
        int gr0 = bm + wm + mb * 16 + r_lo;
        int gr1 = gr0 + 8;
        float bv0 = bias[gr0];
        float bv1 = bias[gr1];
        size_t ro0 = (size_t)gr0 * T_ + bn + wn + c_lo;
        size_t ro1 = (size_t)gr1 * T_ + bn + wn + c_lo;
        #pragma unroll
        for (int nb = 0; nb < 8; nb++) {
            *reinterpret_cast<float2*>(out + ro0 + nb * 8) =
                make_float2(acc[mb][nb][0] + bv0, acc[mb][nb][1] + bv0);
            *reinterpret_cast<float2*>(out + ro1 + nb * 8) =
                make_float2(acc[mb][nb][2] + bv1, acc[mb][nb][3] + bv1);
        }
    }
}

// ---------------------------------------------------------------------------
// Kernel: causal windowed mean via per-group partial sums (all batches).
// ---------------------------------------------------------------------------
__global__ void window_kernel(const float* __restrict__ ff2,
                              float* __restrict__ ret)
{
    __shared__ float s[T_];
    __shared__ float pre[T_ / 4];
    const size_t row = blockIdx.x;
    const float4* p4 = reinterpret_cast<const float4*>(ff2 + row * T_);
    float4* s4 = reinterpret_cast<float4*>(s);
    #pragma unroll
    for (int i = 0; i < 2; i++) {
        int idx = threadIdx.x + i * 256;
        float4 v = p4[idx];
        s4[idx] = v;
        pre[idx] = v.x + v.y + v.z + v.w;
    }
    __syncthreads();
    float4* r4 = reinterpret_cast<float4*>(ret + row * T_);
    #pragma unroll
    for (int i = 0; i < 2; i++) {
        int g = threadIdx.x + i * 256;
        float avg;
        if (g >= 4) {
            float sum = s[4 * g] - s[4 * g - 16]
                      + pre[g - 4] + pre[g - 3] + pre[g - 2] + pre[g - 1];
            avg = sum * 0.0625f;
        } else {
            float sum = s[4 * g];
            for (int q = 0; q < g; q++) sum += pre[q];
            avg = sum / (float)(4 * g + 1);
        }
        r4[g] = make_float4(avg, avg, avg, avg);
    }
}

// ---------------------------------------------------------------------------
// Launcher — 3 streams (hi-prio ff2, lo-prio ff1), 6 events, 10 kernels:
//   main : poolxa_h0(evP0), poolxa_h1(evP1), tap, [evF2] window, [evJ]
//   s_hi : wconv, w12, bias12(evW), [evP0] gemm_ff2_h0, [evP1] gemm_ff2_h1(evF2)
//   s_lo : [evW][evP1] gemm_ff1_all(evJ)
// ---------------------------------------------------------------------------
extern "C" void kernel_launch(void* const* d_in, const int* in_sizes, int n_in,
                              void* d_out, int out_size)
{
    const float* x  = (const float*)d_in[0];
    const float* W1 = (const float*)d_in[1];
    const float* b1 = (const float*)d_in[2];
    const float* W2 = (const float*)d_in[3];
    const float* b2 = (const float*)d_in[4];

    float* out = (float*)d_out;
    float* ret = out;
    float* tap = out + NELEM;
    float* ff1 = out + 2 * NELEM;
    float* ff2 = out + 3 * NELEM;

    static cudaStream_t sHi = nullptr, sLo = nullptr;
    static cudaEvent_t evFork, evW, evP0, evP1, evF2, evJ;
    static __half *xa = nullptr, *w1h, *w12h;
    static float *b12p;
    if (!sHi) {
        int loPri, hiPri;
        cudaDeviceGetStreamPriorityRange(&loPri, &hiPri);
        cudaStreamCreateWithPriority(&sHi, cudaStreamNonBlocking, hiPri);
        cudaStreamCreateWithPriority(&sLo, cudaStreamNonBlocking, loPri);
        cudaEventCreateWithFlags(&evFork, cudaEventDisableTiming);
        cudaEventCreateWithFlags(&evW,    cudaEventDisableTiming);
        cudaEventCreateWithFlags(&evP0,   cudaEventDisableTiming);
        cudaEventCreateWithFlags(&evP1,   cudaEventDisableTiming);
        cudaEventCreateWithFlags(&evF2,   cudaEventDisableTiming);
        cudaEventCreateWithFlags(&evJ,    cudaEventDisableTiming);
        cudaGetSymbolAddress((void**)&xa,   g_xa);
        cudaGetSymbolAddress((void**)&w1h,  g_w1);
        cudaGetSymbolAddress((void**)&w12h, g_w12);
        cudaGetSymbolAddress((void**)&b12p, g_b12);
        cudaFuncSetAttribute(gemm_kernel,
                             cudaFuncAttributeMaxDynamicSharedMemorySize, GEMM_SMEM);
        cudaFuncSetAttribute(w12_kernel,
                             cudaFuncAttributeMaxDynamicSharedMemorySize, W_SMEM);
    }

    const long HCT = (long)HB * CT;   // elements per half

    // fork
    cudaEventRecord(evFork, 0);
    cudaStreamWaitEvent(sHi, evFork, 0);

    // s_hi: weights path
    wconv_kernel<<<(C_ * C_) / 1024, 256, 0, sHi>>>(W1, W2);
    {
        dim3 grid(C_ / 128, C_ / 64);
        w12_kernel<<<grid, 256, W_SMEM, sHi>>>();
    }
    bias12_kernel<<<C_ / 8, 256, 0, sHi>>>(W2, b1, b2);
    cudaEventRecord(evW, sHi);

    // main: pools (xa only)
    poolxa_kernel<<<(int)(HCT / 512), 256>>>(
        reinterpret_cast<const float4*>(x), xa);
    cudaEventRecord(evP0, 0);
    poolxa_kernel<<<(int)(HCT / 512), 256>>>(
        reinterpret_cast<const float4*>(x) + HCT, xa + HCT);
    cudaEventRecord(evP1, 0);

    // main: tap re-expansion (off critical path, overlaps GEMM)
    tap_kernel<<<(int)(NELEM / 1024), 256>>>(tap);

    // s_hi: ff2 GEMMs (high priority -> scheduled first, zero tail waste)
    cudaStreamWaitEvent(sHi, evP0, 0);
    {
        dim3 grid(T_ / 256, C_ / 128, HB);
        gemm_kernel<<<grid, 512, GEMM_SMEM, sHi>>>(w12h, b12p, xa, ff2);
    }
    cudaStreamWaitEvent(sHi, evP1, 0);
    {
        dim3 grid(T_ / 256, C_ / 128, HB);
        gemm_kernel<<<grid, 512, GEMM_SMEM, sHi>>>(w12h, b12p, xa + HCT, ff2 + HCT);
    }
    cudaEventRecord(evF2, sHi);

    // s_lo: ff1 GEMM (backfills ff2 wave tails)
    cudaStreamWaitEvent(sLo, evW, 0);
    cudaStreamWaitEvent(sLo, evP1, 0);
    {
        dim3 grid(T_ / 256, C_ / 128, B_);
        gemm_kernel<<<grid, 512, GEMM_SMEM, sLo>>>(w1h, b1, xa, ff1);
    }
    cudaEventRecord(evJ, sLo);

    // main: window after ff2; join ff1
    cudaStreamWaitEvent(0, evF2, 0);
    window_kernel<<<B_ * C_, 256>>>(ff2, ret);
    cudaStreamWaitEvent(0, evJ, 0);
}

// round 16
// speedup vs baseline: 1.1654x; 1.1654x over previous
#include <cuda_runtime.h>
#include <cuda_fp16.h>
#include <cstdint>

// ---------------------------------------------------------------------------
// Problem constants
// ---------------------------------------------------------------------------
constexpr int B_ = 8;
constexpr int C_ = 1024;     // M and K of both GEMMs
constexpr int T_ = 2048;     // N of both GEMMs
constexpr long NELEM = (long)B_ * C_ * T_;   // 16,777,216
constexpr long CT   = (long)C_ * T_;         // per-batch elements
constexpr int QB   = 2;                      // batches per quarter
constexpr long QCT = (long)QB * CT;          // elements per quarter

// d_out layout: [ret | tap | ff1 | ff2], each NELEM floats.

// ---------------------------------------------------------------------------
// Scratch (device globals)
// ---------------------------------------------------------------------------
__device__ __half g_xa[(size_t)B_ * C_ * T_];   // fp16(tap) : shared B operand
__device__ __half g_w1[(size_t)C_ * C_];
__device__ __half g_w2[(size_t)C_ * C_];
__device__ __half g_w12[(size_t)C_ * C_];       // fp16(W2 @ W1)
__device__ float  g_b12[C_];                    // W2 @ b1 + b2

// ---------------------------------------------------------------------------
// helpers
// ---------------------------------------------------------------------------
__device__ __forceinline__ uint32_t smem_u32(const void* p) {
    uint32_t a;
    asm("{ .reg .u64 t; cvta.to.shared.u64 t, %1; cvt.u32.u64 %0, t; }"
        : "=r"(a) : "l"(p));
    return a;
}
__device__ __forceinline__ void cp_async16(uint32_t sdst, const void* gsrc) {
    asm volatile("cp.async.cg.shared.global [%0], [%1], 16;" :: "r"(sdst), "l"(gsrc));
}
__device__ __forceinline__ void cp_commit() {
    asm volatile("cp.async.commit_group;" ::: "memory");
}
template <int N>
__device__ __forceinline__ void cp_wait() {
    asm volatile("cp.async.wait_group %0;" :: "n"(N) : "memory");
}
__device__ __forceinline__ void ldsm_x4(uint32_t (&r)[4], uint32_t addr) {
    asm volatile("ldmatrix.sync.aligned.m8n8.x4.shared.b16 {%0,%1,%2,%3}, [%4];"
        : "=r"(r[0]), "=r"(r[1]), "=r"(r[2]), "=r"(r[3]) : "r"(addr));
}
__device__ __forceinline__ void ldsm_x4t(uint32_t (&r)[4], uint32_t addr) {
    asm volatile("ldmatrix.sync.aligned.m8n8.x4.trans.shared.b16 {%0,%1,%2,%3}, [%4];"
        : "=r"(r[0]), "=r"(r[1]), "=r"(r[2]), "=r"(r[3]) : "r"(addr));
}
__device__ __forceinline__ void mma_f16(float (&d)[4],
                                        const uint32_t (&a)[4],
                                        const uint32_t* b) {
    asm volatile(
        "mma.sync.aligned.m16n8k16.row.col.f32.f16.f16.f32 "
        "{%0,%1,%2,%3}, {%4,%5,%6,%7}, {%8,%9}, {%0,%1,%2,%3};"
        : "+f"(d[0]), "+f"(d[1]), "+f"(d[2]), "+f"(d[3])
        : "r"(a[0]), "r"(a[1]), "r"(a[2]), "r"(a[3]), "r"(b[0]), "r"(b[1]));
}

// ---------------------------------------------------------------------------
// Kernel: W1, W2 -> fp16 (vectorized)
// ---------------------------------------------------------------------------
__global__ void wconv_kernel(const float* __restrict__ W1,
                             const float* __restrict__ W2)
{
    int i = blockIdx.x * 256 + threadIdx.x;     // float4 index
    float4 v1 = reinterpret_cast<const float4*>(W1)[i];
    float4 v2 = reinterpret_cast<const float4*>(W2)[i];
    __half2 a, b;
    a.x = __float2half(v1.x); a.y = __float2half(v1.y);
    b.x = __float2half(v1.z); b.y = __float2half(v1.w);
    reinterpret_cast<__half2*>(g_w1)[i * 2]     = a;
    reinterpret_cast<__half2*>(g_w1)[i * 2 + 1] = b;
    a.x = __float2half(v2.x); a.y = __float2half(v2.y);
    b.x = __float2half(v2.z); b.y = __float2half(v2.w);
    reinterpret_cast<__half2*>(g_w2)[i * 2]     = a;
    reinterpret_cast<__half2*>(g_w2)[i * 2 + 1] = b;
}

// ---------------------------------------------------------------------------
// Kernel: b12 = W2 @ b1 + b2
// ---------------------------------------------------------------------------
__global__ void bias12_kernel(const float* __restrict__ W2,
                              const float* __restrict__ b1,
                              const float* __restrict__ b2)
{
    int row = blockIdx.x * 8 + (threadIdx.x >> 5);
    int lane = threadIdx.x & 31;
    const float* wr = W2 + (size_t)row * C_;
    float s = 0.0f;
    #pragma unroll 8
    for (int j = lane; j < C_; j += 32) s += wr[j] * b1[j];
    #pragma unroll
    for (int o = 16; o; o >>= 1) s += __shfl_xor_sync(0xFFFFFFFFu, s, o);
    if (lane == 0) g_b12[row] = s + b2[row];
}

// ---------------------------------------------------------------------------
// Kernel: quarter-batch 4:1 mean pool -> tap (fp32) + fp16 into xa
// ---------------------------------------------------------------------------
__global__ void pool_kernel(const float4* __restrict__ x4,
                            float* __restrict__ tap,
                            __half* __restrict__ xa)
{
    long i0 = ((long)blockIdx.x * 256 + threadIdx.x) * 2;
    float4 v0 = x4[i0];
    float4 v1 = x4[i0 + 1];
    float m0 = 0.25f * (v0.x + v0.y + v0.z + v0.w);
    float m1 = 0.25f * (v1.x + v1.y + v1.z + v1.w);
    *reinterpret_cast<float2*>(tap + i0) = make_float2(m0, m1);
    __half2 h; h.x = __float2half(m0); h.y = __float2half(m1);
    *reinterpret_cast<__half2*>(xa + i0) = h;
}

// ---------------------------------------------------------------------------
// W12 GEMM: W12 = fp16(W2 @ W1)
// ---------------------------------------------------------------------------
constexpr int W_KC   = 64;
constexpr int W_ASTR = 144;
constexpr int W_BSTR = 272;
constexpr int W_OFB  = 64 * W_ASTR;               // 9216
constexpr int W_STAGE = W_OFB + W_KC * W_BSTR;    // 26624
constexpr int W_STAGES = 3;
constexpr int W_SMEM = W_STAGES * W_STAGE;        // 79872

__global__ __launch_bounds__(256, 1)
void w12_kernel()
{
    extern __shared__ __align__(128) char smem[];
    const uint32_t sb = smem_u32(smem);
    const int tid  = threadIdx.x;
    const int wid  = tid >> 5;
    const int lane = tid & 31;
    const int bn = blockIdx.x * 128;
    const int bm = blockIdx.y * 64;

    const int wm = (wid & 1) * 32;
    const int wn = (wid >> 1) * 32;

    auto load_stage = [&](int ch, int stg) {
        const int k0 = ch * W_KC;
        const uint32_t st = sb + stg * W_STAGE;
        #pragma unroll
        for (int i = 0; i < 2; i++) {
            int idx = tid + i * 256;
            int r = idx >> 3, c = idx & 7;
            cp_async16(st + r * W_ASTR + c * 16,
                       g_w2 + (size_t)(bm + r) * C_ + k0 + c * 8);
        }
        #pragma unroll
        for (int i = 0; i < 4; i++) {
            int idx = tid + i * 256;
            int r = idx >> 4, c = idx & 15;
            cp_async16(st + W_OFB + r * W_BSTR + c * 16,
                       g_w1 + (size_t)(k0 + r) * C_ + bn + c * 8);
        }
        cp_commit();
    };

    float acc[2][4][4];
    #pragma unroll
    for (int i = 0; i < 2; i++)
        #pragma unroll
        for (int j = 0; j < 4; j++)
            #pragma unroll
            for (int k = 0; k < 4; k++)
                acc[i][j][k] = 0.0f;

    load_stage(0, 0);
    load_stage(1, 1);

    const int lA_row = lane & 15;
    const int lA_kb  = (lane >> 4) * 16;
    const int lB_row = lane & 15;
    const int lB_nc  = (lane >> 4) * 8;

    for (int ch = 0; ch < C_ / W_KC; ch++) {
        cp_wait<W_STAGES - 2>();
        __syncthreads();
        if (ch + W_STAGES - 1 < C_ / W_KC)
            load_stage(ch + W_STAGES - 1, (ch + W_STAGES - 1) % W_STAGES);
        else
            cp_commit();
        const uint32_t st = sb + (ch % W_STAGES) * W_STAGE;

        #pragma unroll
        for (int ks = 0; ks < 4; ks++) {
            uint32_t b[4][2];
            #pragma unroll
            for (int nq = 0; nq < 2; nq++) {
                uint32_t r[4];
                uint32_t off = (uint32_t)((ks * 16 + lB_row) * W_BSTR
                                          + (wn + nq * 16 + lB_nc) * 2);
                ldsm_x4t(r, st + W_OFB + off);
                b[nq * 2 + 0][0] = r[0]; b[nq * 2 + 0][1] = r[1];
                b[nq * 2 + 1][0] = r[2]; b[nq * 2 + 1][1] = r[3];
            }
            #pragma unroll
            for (int mb = 0; mb < 2; mb++) {
                uint32_t a4[4];
                uint32_t off = (uint32_t)((wm + mb * 16 + lA_row) * W_ASTR
                                          + ks * 32 + lA_kb);
                ldsm_x4(a4, st + off);
                #pragma unroll
                for (int nb = 0; nb < 4; nb++)
                    mma_f16(acc[mb][nb], a4, b[nb]);
            }
        }
    }

    const int r_lo = lane >> 2;
    const int c_lo = (lane & 3) * 2;
    #pragma unroll
    for (int mb = 0; mb < 2; mb++) {
        int gr0 = bm + wm + mb * 16 + r_lo;
        int gr1 = gr0 + 8;
        #pragma unroll
        for (int nb = 0; nb < 4; nb++) {
            int col = bn + wn + nb * 8 + c_lo;
            __half2 h0; h0.x = __float2half(acc[mb][nb][0]);
                        h0.y = __float2half(acc[mb][nb][1]);
            __half2 h1; h1.x = __float2half(acc[mb][nb][2]);
                        h1.y = __float2half(acc[mb][nb][3]);
            *reinterpret_cast<__half2*>(g_w12 + (size_t)gr0 * C_ + col) = h0;
            *reinterpret_cast<__half2*>(g_w12 + (size_t)gr1 * C_ + col) = h1;
        }
    }
}

// ---------------------------------------------------------------------------
// Quarter GEMM (512-thr floor config): grid (T/256, C/128, 2*QB).
//   z: batch = z>>1 (within quarter), z&1: 0 -> ff1 (W1,b1), 1 -> ff2 (W12,b12)
// CTA tile 128x256, KC=32, 4-stage cp.async, 16 warps 4(M)x4(N), tile 32x64.
// ---------------------------------------------------------------------------
constexpr int KC = 32;
constexpr int A_STR = 80;
constexpr int B_STR = 528;
constexpr int OF_A = 0;
constexpr int OF_B = 128 * A_STR;                 // 10240
constexpr int STAGE_BYTES = OF_B + KC * B_STR;    // 27136
constexpr int STAGES = 4;
constexpr int GEMM_SMEM = STAGES * STAGE_BYTES;   // 108544
constexpr int NCHUNK = C_ / KC;                   // 32

__global__ __launch_bounds__(512, 1)
void gemm_kernel(const float* __restrict__ b1,
                 const __half* __restrict__ xa_q,   // quarter base
                 float* __restrict__ ff1_q,
                 float* __restrict__ ff2_q)
{
    extern __shared__ __align__(128) char smem[];
    const uint32_t sb = smem_u32(smem);

    const int tid  = threadIdx.x;
    const int wid  = tid >> 5;
    const int lane = tid & 31;
    const int bn = blockIdx.x * 256;
    const int bm = blockIdx.y * 128;
    const int batch = blockIdx.z >> 1;
    const bool second = (blockIdx.z & 1);

    const __half* W    = second ? g_w12 : g_w1;
    const float*  bias = second ? g_b12 : b1;
    float* out = (second ? ff2_q : ff1_q) + (size_t)batch * CT;
    const __half* Xb = xa_q + (size_t)batch * CT;

    const int wm = (wid & 3) * 32;
    const int wn = (wid >> 2) * 64;

    const int a_r = tid >> 2;
    const int a_c = tid & 3;
    const int b_k = tid >> 5;
    const int b_c = tid & 31;

    auto load_stage = [&](int ch, int stg) {
        const int k0 = ch * KC;
        const uint32_t st = sb + stg * STAGE_BYTES;
        cp_async16(st + OF_A + a_r * A_STR + a_c * 16,
                   W + (size_t)(bm + a_r) * C_ + k0 + a_c * 8);
        #pragma unroll
        for (int i = 0; i < 2; i++) {
            int kr = b_k + i * 16;
            cp_async16(st + OF_B + kr * B_STR + b_c * 16,
                       Xb + (size_t)(k0 + kr) * T_ + bn + b_c * 8);
        }
        cp_commit();
    };

    float acc[2][8][4];
    #pragma unroll
    for (int i = 0; i < 2; i++)
        #pragma unroll
        for (int j = 0; j < 8; j++)
            #pragma unroll
            for (int k = 0; k < 4; k++)
                acc[i][j][k] = 0.0f;

    load_stage(0, 0);
    load_stage(1, 1);
    load_stage(2, 2);

    const int lA_row = lane & 15;
    const int lA_kb  = (lane >> 4) * 16;
    const int lB_row = lane & 15;
    const int lB_nc  = (lane >> 4) * 8;

    for (int ch = 0; ch < NCHUNK; ch++) {
        cp_wait<STAGES - 2>();
        __syncthreads();

        if (ch + STAGES - 1 < NCHUNK)
            load_stage(ch + STAGES - 1, (ch + STAGES - 1) % STAGES);
        else
            cp_commit();

        const uint32_t st = sb + (ch % STAGES) * STAGE_BYTES;

        #pragma unroll
        for (int ks = 0; ks < 2; ks++) {
            uint32_t b[8][2];
            #pragma unroll
            for (int nq = 0; nq < 4; nq++) {
                uint32_t r[4];
                uint32_t off = (uint32_t)((ks * 16 + lB_row) * B_STR
                                          + (wn + nq * 16 + lB_nc) * 2);
                ldsm_x4t(r, st + OF_B + off);
                b[nq * 2 + 0][0] = r[0]; b[nq * 2 + 0][1] = r[1];
                b[nq * 2 + 1][0] = r[2]; b[nq * 2 + 1][1] = r[3];
            }
            #pragma unroll
            for (int mb = 0; mb < 2; mb++) {
                uint32_t a4[4];
                uint32_t offA = (uint32_t)((wm + mb * 16 + lA_row) * A_STR
                                           + ks * 32 + lA_kb);
                ldsm_x4(a4, st + OF_A + offA);
                #pragma unroll
                for (int nb = 0; nb < 8; nb++)
                    mma_f16(acc[mb][nb], a4, b[nb]);
            }
        }
    }

    const int r_lo = lane >> 2;
    const int c_lo = (lane & 3) * 2;
    #pragma unroll
    for (int mb = 0; mb < 2; mb++) {
        int gr0 = bm + wm + mb * 16 + r_lo;
        int gr1 = gr0 + 8;
        float bv0 = bias[gr0];
        float bv1 = bias[gr1];
        size_t ro0 = (size_t)gr0 * T_ + bn + wn + c_lo;
        size_t ro1 = (size_t)gr1 * T_ + bn + wn + c_lo;
        #pragma unroll
        for (int nb = 0; nb < 8; nb++) {
            *reinterpret_cast<float2*>(out + ro0 + nb * 8) =
                make_float2(acc[mb][nb][0] + bv0, acc[mb][nb][1] + bv0);
            *reinterpret_cast<float2*>(out + ro1 + nb * 8) =
                make_float2(acc[mb][nb][2] + bv1, acc[mb][nb][3] + bv1);
        }
    }
}

// ---------------------------------------------------------------------------
// Kernel: half-batch causal windowed mean via per-group partial sums.
// ---------------------------------------------------------------------------
__global__ void window_kernel(const float* __restrict__ ff2h,
                              float* __restrict__ reth)
{
    __shared__ float s[T_];
    __shared__ float pre[T_ / 4];
    const size_t row = blockIdx.x;
    const float4* p4 = reinterpret_cast<const float4*>(ff2h + row * T_);
    float4* s4 = reinterpret_cast<float4*>(s);
    #pragma unroll
    for (int i = 0; i < 2; i++) {
        int idx = threadIdx.x + i * 256;
        float4 v = p4[idx];
        s4[idx] = v;
        pre[idx] = v.x + v.y + v.z + v.w;
    }
    __syncthreads();
    float4* r4 = reinterpret_cast<float4*>(reth + row * T_);
    #pragma unroll
    for (int i = 0; i < 2; i++) {
        int g = threadIdx.x + i * 256;
        float avg;
        if (g >= 4) {
            float sum = s[4 * g] - s[4 * g - 16]
                      + pre[g - 4] + pre[g - 3] + pre[g - 2] + pre[g - 1];
            avg = sum * 0.0625f;
        } else {
            float sum = s[4 * g];
            for (int q = 0; q < g; q++) sum += pre[q];
            avg = sum / (float)(4 * g + 1);
        }
        r4[g] = make_float4(avg, avg, avg, avg);
    }
}

// ---------------------------------------------------------------------------
// Launcher — quarter-pipelined, 3 streams, 10 events, 13 kernels:
//   main : poolQ0..Q3 (evP0..3), window_h0 (evG0,evG1), window_h1 (evG2,evG3)
//   s2   : wconv, w12, bias12 (evW), gemmQ1 (evP1), gemmQ3 (evP3)
//   s1   : gemmQ0 (evW,evP0), gemmQ2 (evP2)
// ---------------------------------------------------------------------------
extern "C" void kernel_launch(void* const* d_in, const int* in_sizes, int n_in,
                              void* d_out, int out_size)
{
    const float* x  = (const float*)d_in[0];
    const float* W1 = (const float*)d_in[1];
    const float* b1 = (const float*)d_in[2];
    const float* W2 = (const float*)d_in[3];
    const float* b2 = (const float*)d_in[4];

    float* out = (float*)d_out;
    float* ret = out;
    float* tap = out + NELEM;
    float* ff1 = out + 2 * NELEM;
    float* ff2 = out + 3 * NELEM;

    static cudaStream_t s1 = nullptr, s2 = nullptr;
    static cudaEvent_t evFork, evW, evP[4], evG[4];
    static __half* xa = nullptr;
    if (!s1) {
        cudaStreamCreateWithFlags(&s1, cudaStreamNonBlocking);
        cudaStreamCreateWithFlags(&s2, cudaStreamNonBlocking);
        cudaEventCreateWithFlags(&evFork, cudaEventDisableTiming);
        cudaEventCreateWithFlags(&evW,    cudaEventDisableTiming);
        for (int q = 0; q < 4; q++) {
            cudaEventCreateWithFlags(&evP[q], cudaEventDisableTiming);
            cudaEventCreateWithFlags(&evG[q], cudaEventDisableTiming);
        }
        cudaGetSymbolAddress((void**)&xa, g_xa);
        cudaFuncSetAttribute(gemm_kernel,
                             cudaFuncAttributeMaxDynamicSharedMemorySize, GEMM_SMEM);
        cudaFuncSetAttribute(w12_kernel,
                             cudaFuncAttributeMaxDynamicSharedMemorySize, W_SMEM);
    }

    // fork
    cudaEventRecord(evFork, 0);
    cudaStreamWaitEvent(s1, evFork, 0);
    cudaStreamWaitEvent(s2, evFork, 0);

    // s2: weights path
    wconv_kernel<<<(C_ * C_) / 1024, 256, 0, s2>>>(W1, W2);
    {
        dim3 grid(C_ / 128, C_ / 64);
        w12_kernel<<<grid, 256, W_SMEM, s2>>>();
    }
    bias12_kernel<<<C_ / 8, 256, 0, s2>>>(W2, b1, b2);
    cudaEventRecord(evW, s2);
    cudaStreamWaitEvent(s1, evW, 0);

    // main: pools per quarter
    for (int q = 0; q < 4; q++) {
        pool_kernel<<<(int)(QCT / 512), 256>>>(
            reinterpret_cast<const float4*>(x) + q * QCT,
            tap + q * QCT, xa + q * QCT);
        cudaEventRecord(evP[q], 0);
    }

    // gemm quarters alternating s1/s2 (s2 already ordered after weights)
    for (int q = 0; q < 4; q++) {
        cudaStream_t gs = (q & 1) ? s2 : s1;
        cudaStreamWaitEvent(gs, evP[q], 0);
        dim3 grid(T_ / 256, C_ / 128, 2 * QB);
        gemm_kernel<<<grid, 512, GEMM_SMEM, gs>>>(
            b1, xa + q * QCT, ff1 + q * QCT, ff2 + q * QCT);
        cudaEventRecord(evG[q], gs);
    }

    // main: windows per half (h0 overlaps gemm Q2/Q3)
    cudaStreamWaitEvent(0, evG[0], 0);
    cudaStreamWaitEvent(0, evG[1], 0);
    window_kernel<<<2 * QB * C_, 256>>>(ff2, ret);
    cudaStreamWaitEvent(0, evG[2], 0);
    cudaStreamWaitEvent(0, evG[3], 0);
    window_kernel<<<2 * QB * C_, 256>>>(ff2 + 2 * QCT, ret + 2 * QCT);
}